// round 14
// baseline (speedup 1.0000x reference)
#include <cuda_runtime.h>
#include <math.h>

#define ADIM 6
#define ZDIM 32
#define HDIM 512
#define EDIM 1024
#define BATCH 256
#define TSTEPS 64
#define NTHR 512
#define SMEMB 53248

#define OFF_Z  (BATCH*TSTEPS*HDIM)
#define OFF_PM (OFF_Z + BATCH*TSTEPS*ZDIM)
#define OFF_PS (OFF_PM + BATCH*TSTEPS*ZDIM)
#define OFF_QM (OFF_PS + BATCH*TSTEPS*ZDIM)
#define OFF_QS (OFF_QM + BATCH*TSTEPS*ZDIM)

// scratch. pre* layout: [t][b][h]
__device__ __align__(128) float g_preAZ[TSTEPS*BATCH*HDIM];
__device__ __align__(128) float g_preHA[TSTEPS*BATCH*HDIM];
__device__ __align__(128) float g_preHE[TSTEPS*BATCH*HDIM];
__device__ __align__(128) float g_Gp[3][BATCH*3072];
__device__ __align__(128) float g_Hp[8][BATCH*1024];
__device__ __align__(128) float g_h[BATCH*HDIM];
__device__ __align__(128) float g_z[BATCH*ZDIM];
__device__ __align__(128) float g_WazzT[ZDIM*HDIM];
// pre-split tf32 operands (hi/lo stored as fp32 bit patterns)
__device__ __align__(128) float g_WihH[1536*HDIM], g_WihL[1536*HDIM];
__device__ __align__(128) float g_WhhH[1536*HDIM], g_WhhL[1536*HDIM];
__device__ __align__(128) float g_WhaH[HDIM*HDIM], g_WhaL[HDIM*HDIM];
__device__ __align__(128) float g_WheH[HDIM*HDIM], g_WheL[HDIM*HDIM];
__device__ __align__(128) float g_hH[BATCH*HDIM], g_hL[BATCH*HDIM];
__device__ __align__(128) float g_xH[BATCH*HDIM], g_xL[BATCH*HDIM];
__device__ volatile unsigned g_arrive = 0;
__device__ volatile unsigned g_epoch = 0;

__device__ __forceinline__ float sigmoidf_(float x) { return 1.f/(1.f+expf(-x)); }
__device__ __forceinline__ float softplusf_(float x) {
    return fmaxf(x, 0.f) + log1pf(expf(-fabsf(x)));
}
__device__ __forceinline__ float4 ld4(const float* p) { return *(const float4*)p; }
__device__ __forceinline__ float4 ld4cg(const float* p) { return __ldcg((const float4*)p); }
__device__ __forceinline__ void st2cg(float* p, float2 v) { __stcg((float2*)p, v); }

__device__ __forceinline__ unsigned tf32of(float x) {
    unsigned u; asm("cvt.rna.tf32.f32 %0, %1;" : "=r"(u) : "f"(x)); return u;
}
__device__ __forceinline__ void split_tf32(float x, unsigned &hi, unsigned &lo) {
    hi = tf32of(x);
    lo = tf32of(x - __uint_as_float(hi));
}
__device__ __forceinline__ void mma_tf32(float4 &d, unsigned a0, unsigned a1,
                                         unsigned a2, unsigned a3,
                                         unsigned b0, unsigned b1) {
    asm volatile(
        "mma.sync.aligned.m16n8k8.row.col.f32.tf32.tf32.f32 "
        "{%0,%1,%2,%3},{%4,%5,%6,%7},{%8,%9},{%0,%1,%2,%3};"
        : "+f"(d.x), "+f"(d.y), "+f"(d.z), "+f"(d.w)
        : "r"(a0), "r"(a1), "r"(a2), "r"(a3), "r"(b0), "r"(b1));
}

// Fence-free grid barrier (scoped atomics, no CCTL.IVALL).
__device__ __forceinline__ void gsync(int G) {
    __syncthreads();
    if (threadIdx.x == 0) {
        unsigned e = g_epoch;
        unsigned old;
        asm volatile("atom.acq_rel.gpu.global.add.u32 %0, [%1], %2;"
                     : "=r"(old) : "l"((unsigned*)&g_arrive), "r"(1u) : "memory");
        if (old == (unsigned)(G - 1)) {
            g_arrive = 0;
            asm volatile("st.release.gpu.global.u32 [%0], %1;"
                         :: "l"((unsigned*)&g_epoch), "r"(e + 1u) : "memory");
        } else {
            unsigned cur;
            do {
                __nanosleep(32);
                asm volatile("ld.acquire.gpu.global.u32 %0, [%1];"
                             : "=r"(cur) : "l"((unsigned*)&g_epoch) : "memory");
            } while (cur == e);
        }
    }
    __syncthreads();
}

// ---------------------------------------------------------------------------
// Pre-split 128x128 tile GEMM on tensor cores (tf32 3-product).
// A/B supplied as hi/lo pairs (layout [row][k], lda/ldb). Activation (A) loads
// use .cg; weight (B) loads use L1. Inner loop: pure LDS + MMA, zero cvt.
// ---------------------------------------------------------------------------
__device__ __forceinline__ void gemm128_ps(
    const float* __restrict__ Ah_, const float* __restrict__ Al_, int lda,
    const float* __restrict__ Bh_, const float* __restrict__ Bl_, int ldb,
    int KT, float* sm, float4 (&acc)[2][4])
{
    float* Ash = sm;
    float* Asl = sm + 2112;
    float* Bsh = sm + 4224;
    float* Bsl = sm + 6336;
    const int tid = threadIdx.x;
    const int lr = tid >> 2, lk = (tid & 3) << 2;
    const int lane = tid & 31, warp = tid >> 5;
    const int wm = (warp & 3) * 32, wn = (warp >> 2) * 32;
    const int gid = lane >> 2, tig = lane & 3;
    const float* Aph = Ah_ + lr*lda + lk;
    const float* Apl = Al_ + lr*lda + lk;
    const float* Bph = Bh_ + lr*ldb + lk;
    const float* Bpl = Bl_ + lr*ldb + lk;
    float4 avh = ld4cg(Aph), avl = ld4cg(Apl);
    float4 bvh = ld4(Bph),   bvl = ld4(Bpl);
    #pragma unroll 1
    for (int kt = 1; kt <= KT; kt++) {
        __syncthreads();
        Ash[(lk+0)*132+lr]=avh.x; Ash[(lk+1)*132+lr]=avh.y; Ash[(lk+2)*132+lr]=avh.z; Ash[(lk+3)*132+lr]=avh.w;
        Asl[(lk+0)*132+lr]=avl.x; Asl[(lk+1)*132+lr]=avl.y; Asl[(lk+2)*132+lr]=avl.z; Asl[(lk+3)*132+lr]=avl.w;
        Bsh[(lk+0)*132+lr]=bvh.x; Bsh[(lk+1)*132+lr]=bvh.y; Bsh[(lk+2)*132+lr]=bvh.z; Bsh[(lk+3)*132+lr]=bvh.w;
        Bsl[(lk+0)*132+lr]=bvl.x; Bsl[(lk+1)*132+lr]=bvl.y; Bsl[(lk+2)*132+lr]=bvl.z; Bsl[(lk+3)*132+lr]=bvl.w;
        __syncthreads();
        if (kt < KT) {
            avh = ld4cg(Aph + kt*16); avl = ld4cg(Apl + kt*16);
            bvh = ld4(Bph + kt*16);   bvl = ld4(Bpl + kt*16);
        }
        #pragma unroll
        for (int kq = 0; kq < 2; kq++) {
            const int kA = kq*8 + tig;
            unsigned ah[2][4], al[2][4];
            #pragma unroll
            for (int i = 0; i < 2; i++) {
                int mi = wm + i*16 + gid;
                ah[i][0] = __float_as_uint(Ash[kA*132 + mi]);
                ah[i][1] = __float_as_uint(Ash[kA*132 + mi + 8]);
                ah[i][2] = __float_as_uint(Ash[(kA+4)*132 + mi]);
                ah[i][3] = __float_as_uint(Ash[(kA+4)*132 + mi + 8]);
                al[i][0] = __float_as_uint(Asl[kA*132 + mi]);
                al[i][1] = __float_as_uint(Asl[kA*132 + mi + 8]);
                al[i][2] = __float_as_uint(Asl[(kA+4)*132 + mi]);
                al[i][3] = __float_as_uint(Asl[(kA+4)*132 + mi + 8]);
            }
            unsigned bh[4][2], bl[4][2];
            #pragma unroll
            for (int j = 0; j < 4; j++) {
                int nj = wn + j*8 + gid;
                bh[j][0] = __float_as_uint(Bsh[kA*132 + nj]);
                bh[j][1] = __float_as_uint(Bsh[(kA+4)*132 + nj]);
                bl[j][0] = __float_as_uint(Bsl[kA*132 + nj]);
                bl[j][1] = __float_as_uint(Bsl[(kA+4)*132 + nj]);
            }
            #pragma unroll
            for (int i = 0; i < 2; i++)
                #pragma unroll
                for (int j = 0; j < 4; j++) {
                    mma_tf32(acc[i][j], ah[i][0],ah[i][1],ah[i][2],ah[i][3], bh[j][0],bh[j][1]);
                    mma_tf32(acc[i][j], ah[i][0],ah[i][1],ah[i][2],ah[i][3], bl[j][0],bl[j][1]);
                    mma_tf32(acc[i][j], al[i][0],al[i][1],al[i][2],al[i][3], bh[j][0],bh[j][1]);
                }
        }
    }
}

// On-the-fly split version (prologue preHE only; runs once).
__device__ __forceinline__ void gemm128_tc(
    const float* __restrict__ A, int lda, const float* __restrict__ B, int ldb,
    int KT, float* As, float* Bs, float4 (&acc)[2][4])
{
    const int tid = threadIdx.x;
    const int lr = tid >> 2, lk = (tid & 3) << 2;
    const int lane = tid & 31, warp = tid >> 5;
    const int wm = (warp & 3) * 32, wn = (warp >> 2) * 32;
    const int gid = lane >> 2, tig = lane & 3;
    const float* Ap = A + lr*lda + lk;
    const float* Bp = B + lr*ldb + lk;
    float4 av = ld4(Ap), bv = ld4(Bp);
    #pragma unroll 1
    for (int kt = 1; kt <= KT; kt++) {
        __syncthreads();
        As[(lk+0)*132+lr]=av.x; As[(lk+1)*132+lr]=av.y; As[(lk+2)*132+lr]=av.z; As[(lk+3)*132+lr]=av.w;
        Bs[(lk+0)*132+lr]=bv.x; Bs[(lk+1)*132+lr]=bv.y; Bs[(lk+2)*132+lr]=bv.z; Bs[(lk+3)*132+lr]=bv.w;
        __syncthreads();
        if (kt < KT) { av = ld4(Ap + kt*16); bv = ld4(Bp + kt*16); }
        #pragma unroll
        for (int kq = 0; kq < 2; kq++) {
            const int kA = kq*8 + tig;
            unsigned ah[2][4], al[2][4];
            #pragma unroll
            for (int i = 0; i < 2; i++) {
                int mi = wm + i*16 + gid;
                split_tf32(As[kA*132 + mi],        ah[i][0], al[i][0]);
                split_tf32(As[kA*132 + mi + 8],    ah[i][1], al[i][1]);
                split_tf32(As[(kA+4)*132 + mi],    ah[i][2], al[i][2]);
                split_tf32(As[(kA+4)*132 + mi + 8],ah[i][3], al[i][3]);
            }
            unsigned bh[4][2], bl[4][2];
            #pragma unroll
            for (int j = 0; j < 4; j++) {
                int nj = wn + j*8 + gid;
                split_tf32(Bs[kA*132 + nj],     bh[j][0], bl[j][0]);
                split_tf32(Bs[(kA+4)*132 + nj], bh[j][1], bl[j][1]);
            }
            #pragma unroll
            for (int i = 0; i < 2; i++)
                #pragma unroll
                for (int j = 0; j < 4; j++) {
                    mma_tf32(acc[i][j], ah[i][0],ah[i][1],ah[i][2],ah[i][3], bh[j][0],bh[j][1]);
                    mma_tf32(acc[i][j], ah[i][0],ah[i][1],ah[i][2],ah[i][3], bl[j][0],bl[j][1]);
                    mma_tf32(acc[i][j], al[i][0],al[i][1],al[i][2],al[i][3], bh[j][0],bh[j][1]);
                }
        }
    }
}

__device__ __forceinline__ float gru1(float ir, float iz, float inn,
                                      float hr, float hz, float hn, float hp) {
    float rr = sigmoidf_(ir + hr);
    float u = sigmoidf_(iz + hz);
    float n = tanhf(inn + rr*hn);
    return (1.f - u)*n + u*hp;
}

__constant__ int c_kofs[3] = {0, 176, 352};
__constant__ int c_kcnt[3] = {11, 11, 10};

__global__ __launch_bounds__(NTHR, 1) void rssm_kernel(
    const float* __restrict__ prev_z, const float* __restrict__ prev_h,
    const float* __restrict__ actions, const float* __restrict__ emb,
    const float* __restrict__ dones, const float* __restrict__ post_noise,
    const float* __restrict__ W_az, const float* __restrict__ b_az,
    const float* __restrict__ W_ih, const float* __restrict__ W_hh,
    const float* __restrict__ b_ih, const float* __restrict__ b_hh,
    const float* __restrict__ W_ha, const float* __restrict__ b_ha,
    const float* __restrict__ W_prior, const float* __restrict__ b_prior,
    const float* __restrict__ W_he, const float* __restrict__ b_he,
    const float* __restrict__ W_post, const float* __restrict__ b_post,
    float* __restrict__ out)
{
    extern __shared__ __align__(16) float sm[];
    const int tid = threadIdx.x, bid = blockIdx.x, G = gridDim.x;
    const int gthr = G*NTHR, gtid = bid*NTHR + tid;
    const int lane = tid & 31, warp = tid >> 5;
    const int wm = (warp & 3) * 32, wn = (warp >> 2) * 32;
    const int gid = lane >> 2, tig = lane & 3;

    // ===== P0: init, weight pre-split, action projections, preHE =====
    for (int i = gtid; i < BATCH*HDIM; i += gthr) {
        float v = prev_h[i];
        g_h[i] = v;
        unsigned hh, hl; split_tf32(v, hh, hl);
        g_hH[i] = __uint_as_float(hh); g_hL[i] = __uint_as_float(hl);
    }
    for (int i = gtid; i < BATCH*ZDIM; i += gthr) g_z[i] = prev_z[i];
    for (int i = gtid; i < 1536*HDIM; i += gthr) {
        unsigned hh, hl;
        split_tf32(W_ih[i], hh, hl);
        g_WihH[i] = __uint_as_float(hh); g_WihL[i] = __uint_as_float(hl);
        split_tf32(W_hh[i], hh, hl);
        g_WhhH[i] = __uint_as_float(hh); g_WhhL[i] = __uint_as_float(hl);
    }
    for (int i = gtid; i < HDIM*HDIM; i += gthr) {
        int n = i >> 9, k = i & 511;
        unsigned hh, hl;
        split_tf32(W_ha[n*(HDIM+ADIM) + k], hh, hl);
        g_WhaH[i] = __uint_as_float(hh); g_WhaL[i] = __uint_as_float(hl);
        split_tf32(W_he[n*1536 + k], hh, hl);
        g_WheH[i] = __uint_as_float(hh); g_WheL[i] = __uint_as_float(hl);
    }
    for (int i = gtid; i < ZDIM*HDIM; i += gthr)
        g_WazzT[i] = W_az[(i & 511)*(ZDIM+ADIM) + (i >> 9)];
    for (int tt = bid; tt < TSTEPS; tt += G) {
        float* waz = sm, *wha = sm + 3072, *actS = sm + 6144;
        __syncthreads();
        for (int e = tid; e < HDIM*ADIM; e += NTHR) {
            int h = e / ADIM, j = e - h*ADIM;
            waz[e] = W_az[h*(ZDIM+ADIM) + ZDIM + j];
            wha[e] = W_ha[h*(HDIM+ADIM) + HDIM + j];
        }
        for (int e = tid; e < BATCH*ADIM; e += NTHR) {
            int b = e / ADIM, j = e - b*ADIM;
            actS[e] = actions[(b*TSTEPS + tt)*ADIM + j];
        }
        __syncthreads();
        for (int e = tid; e < BATCH*HDIM; e += NTHR) {
            int b = e >> 9, h = e & 511;
            float pa = b_az[h], ph = b_ha[h];
            #pragma unroll
            for (int j = 0; j < ADIM; j++) {
                float a = actS[b*ADIM + j];
                pa += a * waz[h*ADIM + j];
                ph += a * wha[h*ADIM + j];
            }
            int o = (tt*BATCH + b)*HDIM + h;
            g_preAZ[o] = pa; g_preHA[o] = ph;
        }
        __syncthreads();
    }
    // preHE: 512 tasks = 128 m-tiles x 4 n-tiles, K=1024 (KT=64)
    for (int task = bid; task < 512; task += G) {
        int n = task & 3, m = task >> 2;
        float4 acc[2][4] = {};
        gemm128_tc(emb + (size_t)m*128*EDIM, EDIM,
                   W_he + (size_t)n*128*1536 + 512, 1536, 64, sm, sm + 2112, acc);
        #pragma unroll
        for (int i = 0; i < 2; i++)
            #pragma unroll
            for (int j = 0; j < 4; j++) {
                int row = m*128 + wm + i*16 + gid;
                int col = n*128 + wn + j*8 + tig*2;
                float b0 = b_he[col], b1 = b_he[col+1];
                int o0 = ((row & 63)*BATCH + (row >> 6))*HDIM + col;
                int r8 = row + 8;
                int o1 = ((r8 & 63)*BATCH + (r8 >> 6))*HDIM + col;
                *(float2*)(g_preHE + o0) = make_float2(acc[i][j].x + b0, acc[i][j].y + b1);
                *(float2*)(g_preHE + o1) = make_float2(acc[i][j].z + b0, acc[i][j].w + b1);
            }
    }
    gsync(G);
    // ===== P1: x(0) =====
    for (int i = gtid; i < BATCH*HDIM; i += gthr) {
        int b = i >> 9, c = i & 511;
        float d = 1.f - dones[b*TSTEPS];
        float acx = g_preAZ[b*HDIM + c];
        #pragma unroll 8
        for (int k = 0; k < ZDIM; k++)
            acx += (g_z[b*ZDIM + k]*d) * g_WazzT[k*HDIM + c];
        acx = fmaxf(acx, 0.f);
        unsigned xh, xl; split_tf32(acx, xh, xl);
        __stcg(g_xH + i, __uint_as_float(xh));
        __stcg(g_xL + i, __uint_as_float(xl));
    }
    gsync(G);

    for (int t = 0; t < TSTEPS; t++) {
        // ---- A: gate partials. 144 tasks = 48 tiles(128x128) x Ksplit3 ----
        for (int task = bid; task < 144; task += G) {
            int kc = task % 3, tile = task / 3;
            int n = tile % 24, m = tile / 24;
            int ko = c_kofs[kc];
            size_t ao = (size_t)m*128*HDIM + ko;
            const float* AH = ((n < 12) ? g_xH : g_hH) + ao;
            const float* AL = ((n < 12) ? g_xL : g_hL) + ao;
            size_t bo = ((n < 12) ? (size_t)n : (size_t)(n-12))*128*HDIM + ko;
            const float* BH = ((n < 12) ? g_WihH : g_WhhH) + bo;
            const float* BL = ((n < 12) ? g_WihL : g_WhhL) + bo;
            float4 acc[2][4] = {};
            gemm128_ps(AH, AL, HDIM, BH, BL, HDIM, c_kcnt[kc], sm, acc);
            #pragma unroll
            for (int i = 0; i < 2; i++)
                #pragma unroll
                for (int j = 0; j < 4; j++) {
                    int row = m*128 + wm + i*16 + gid;
                    int col = n*128 + wn + j*8 + tig*2;
                    st2cg(&g_Gp[kc][row*3072 + col], make_float2(acc[i][j].x, acc[i][j].y));
                    st2cg(&g_Gp[kc][(row+8)*3072 + col], make_float2(acc[i][j].z, acc[i][j].w));
                }
        }
        gsync(G);
        // ---- B: combine 3 partials + GRU fuse + h_seq + h split ----
        for (int i = gtid; i < BATCH*HDIM/4; i += gthr) {
            int b = i >> 7, j4 = (i & 127) << 2;
            const float* p0 = g_Gp[0] + b*3072 + j4;
            const float* p1 = g_Gp[1] + b*3072 + j4;
            const float* p2 = g_Gp[2] + b*3072 + j4;
            float4 gg[6];
            #pragma unroll
            for (int q = 0; q < 6; q++) {
                float4 a = ld4cg(p0 + q*512), bb = ld4cg(p1 + q*512), c = ld4cg(p2 + q*512);
                gg[q] = make_float4(a.x+bb.x+c.x, a.y+bb.y+c.y, a.z+bb.z+c.z, a.w+bb.w+c.w);
            }
            float4 bir = ld4(b_ih + j4), biz = ld4(b_ih + 512 + j4), bin = ld4(b_ih + 1024 + j4);
            float4 bhr = ld4(b_hh + j4), bhz = ld4(b_hh + 512 + j4), bhn = ld4(b_hh + 1024 + j4);
            float4 hp = ld4cg(g_h + i*4);
            float4 hv;
            hv.x = gru1(gg[0].x+bir.x, gg[1].x+biz.x, gg[2].x+bin.x, gg[3].x+bhr.x, gg[4].x+bhz.x, gg[5].x+bhn.x, hp.x);
            hv.y = gru1(gg[0].y+bir.y, gg[1].y+biz.y, gg[2].y+bin.y, gg[3].y+bhr.y, gg[4].y+bhz.y, gg[5].y+bhn.y, hp.y);
            hv.z = gru1(gg[0].z+bir.z, gg[1].z+biz.z, gg[2].z+bin.z, gg[3].z+bhr.z, gg[4].z+bhz.z, gg[5].z+bhn.z, hp.z);
            hv.w = gru1(gg[0].w+bir.w, gg[1].w+biz.w, gg[2].w+bin.w, gg[3].w+bhr.w, gg[4].w+bhz.w, gg[5].w+bhn.w, hp.w);
            __stcg((float4*)(g_h + i*4), hv);
            *(float4*)(out + (b*TSTEPS + t)*HDIM + j4) = hv;
            float4 hH4, hL4;
            unsigned uh, ul;
            split_tf32(hv.x, uh, ul); hH4.x = __uint_as_float(uh); hL4.x = __uint_as_float(ul);
            split_tf32(hv.y, uh, ul); hH4.y = __uint_as_float(uh); hL4.y = __uint_as_float(ul);
            split_tf32(hv.z, uh, ul); hH4.z = __uint_as_float(uh); hL4.z = __uint_as_float(ul);
            split_tf32(hv.w, uh, ul); hH4.w = __uint_as_float(uh); hL4.w = __uint_as_float(ul);
            __stcg((float4*)(g_hH + i*4), hH4);
            __stcg((float4*)(g_hL + i*4), hL4);
        }
        gsync(G);
        // ---- C: hahe partials. 128 tasks = 16 tiles(128x128) x Ksplit8 (K=64) ----
        for (int task = bid; task < 128; task += G) {
            int kc = task & 7, tile = task >> 3;
            int n = tile & 7, m = tile >> 3;
            size_t ao = (size_t)m*128*HDIM + kc*64;
            size_t bo = ((n < 4) ? (size_t)n : (size_t)(n-4))*128*HDIM + kc*64;
            const float* BH = ((n < 4) ? g_WhaH : g_WheH) + bo;
            const float* BL = ((n < 4) ? g_WhaL : g_WheL) + bo;
            float4 acc[2][4] = {};
            gemm128_ps(g_hH + ao, g_hL + ao, HDIM, BH, BL, HDIM, 4, sm, acc);
            #pragma unroll
            for (int i = 0; i < 2; i++)
                #pragma unroll
                for (int j = 0; j < 4; j++) {
                    int row = m*128 + wm + i*16 + gid;
                    int col = n*128 + wn + j*8 + tig*2;
                    st2cg(&g_Hp[kc][row*1024 + col], make_float2(acc[i][j].x, acc[i][j].y));
                    st2cg(&g_Hp[kc][(row+8)*1024 + col], make_float2(acc[i][j].z, acc[i][j].w));
                }
        }
        gsync(G);
        // ---- D: 64 tasks x 4 rows: combine+relu, heads, z, x[t+1] ----
        for (int task = bid; task < 64; task += G) {
            int r0 = task*4;
            float* A8 = sm;          // 4 x 1028
            float* Ws = sm + 4112;   // 128 x 68
            __syncthreads();
            for (int e = tid; e < 4*1024; e += NTHR) {
                int r = e >> 10, c = e & 1023;
                int ro = (r0 + r)*1024 + c;
                float v = __ldcg(g_Hp[0]+ro) + __ldcg(g_Hp[1]+ro)
                        + __ldcg(g_Hp[2]+ro) + __ldcg(g_Hp[3]+ro)
                        + __ldcg(g_Hp[4]+ro) + __ldcg(g_Hp[5]+ro)
                        + __ldcg(g_Hp[6]+ro) + __ldcg(g_Hp[7]+ro);
                v += (c < 512) ? g_preHA[(t*BATCH + r0+r)*HDIM + c]
                               : g_preHE[(t*BATCH + r0+r)*HDIM + c - 512];
                A8[r*1028 + c] = fmaxf(v, 0.f);
            }
            const int c = tid & 127, rg = tid >> 7;
            const int aoff = (c < 64) ? 0 : 512;
            float acc = 0.f;
            for (int ch = 0; ch < 8; ch++) {
                __syncthreads();
                for (int e = tid; e < 512; e += NTHR) {
                    int c2 = e >> 2, k4 = (e & 3) << 4;
                    const float* Wr = (c2 < 64) ? W_prior + c2*HDIM : W_post + (c2-64)*HDIM;
                    #pragma unroll
                    for (int q = 0; q < 4; q++) {
                        float4 w = ld4(Wr + ch*64 + k4 + q*4);
                        Ws[c2*68 + k4 + q*4]   = w.x; Ws[c2*68 + k4 + q*4+1] = w.y;
                        Ws[c2*68 + k4 + q*4+2] = w.z; Ws[c2*68 + k4 + q*4+3] = w.w;
                    }
                }
                __syncthreads();
                const float* ab = A8 + rg*1028 + aoff + ch*64;
                #pragma unroll
                for (int k4 = 0; k4 < 64; k4 += 4) {
                    float4 w = ld4(Ws + c*68 + k4);
                    float4 a = ld4(ab + k4);
                    acc += a.x*w.x + a.y*w.y + a.z*w.z + a.w*w.w;
                }
            }
            __syncthreads();
            float* Q  = sm;        // 4 x 64 (A8 dead)
            float* zm = sm + 256;  // 4 x 32
            {
                int b = r0 + rg;
                float v = acc + ((c < 64) ? b_prior[c] : b_post[c-64]);
                if (c < 32)       out[OFF_PM + (b*TSTEPS + t)*ZDIM + c] = v;
                else if (c < 64)  out[OFF_PS + (b*TSTEPS + t)*ZDIM + c-32] = softplusf_(v);
                else              Q[rg*64 + (c-64)] = v;
            }
            __syncthreads();
            if (tid < 128) {
                int r = tid >> 5, j = tid & 31, b = r0 + r;
                float qm = Q[r*64 + j];
                float qs = softplusf_(Q[r*64 + 32 + j]);
                float z = qm + qs * post_noise[(b*TSTEPS + t)*ZDIM + j];
                int o = (b*TSTEPS + t)*ZDIM + j;
                out[OFF_QM + o] = qm; out[OFF_QS + o] = qs; out[OFF_Z + o] = z;
                if (t + 1 < TSTEPS)
                    zm[r*32 + j] = z * (1.f - dones[b*TSTEPS + t + 1]);
            }
            __syncthreads();
            if (t + 1 < TSTEPS) {
                for (int e = tid; e < 4*HDIM; e += NTHR) {
                    int r = e >> 9, cc = e & 511;
                    float acx = g_preAZ[((t+1)*BATCH + r0+r)*HDIM + cc];
                    #pragma unroll 8
                    for (int k = 0; k < ZDIM; k++)
                        acx += zm[r*32 + k] * g_WazzT[k*HDIM + cc];
                    acx = fmaxf(acx, 0.f);
                    unsigned xh, xl; split_tf32(acx, xh, xl);
                    int xo = (r0+r)*HDIM + cc;
                    __stcg(g_xH + xo, __uint_as_float(xh));
                    __stcg(g_xL + xo, __uint_as_float(xl));
                }
            }
            __syncthreads();
        }
        if (t + 1 < TSTEPS) gsync(G);
    }
}

extern "C" void kernel_launch(void* const* d_in, const int* in_sizes, int n_in,
                              void* d_out, int out_size) {
    const float* prev_z = (const float*)d_in[0];
    const float* prev_h = (const float*)d_in[1];
    const float* actions = (const float*)d_in[2];
    const float* emb = (const float*)d_in[3];
    const float* dones = (const float*)d_in[4];
    const float* post_noise = (const float*)d_in[6];
    const float* W_az = (const float*)d_in[7];
    const float* b_az = (const float*)d_in[8];
    const float* W_ih = (const float*)d_in[9];
    const float* W_hh = (const float*)d_in[10];
    const float* b_ih = (const float*)d_in[11];
    const float* b_hh = (const float*)d_in[12];
    const float* W_ha = (const float*)d_in[13];
    const float* b_ha = (const float*)d_in[14];
    const float* W_prior = (const float*)d_in[15];
    const float* b_prior = (const float*)d_in[16];
    const float* W_he = (const float*)d_in[17];
    const float* b_he = (const float*)d_in[18];
    const float* W_post = (const float*)d_in[19];
    const float* b_post = (const float*)d_in[20];
    float* out = (float*)d_out;

    cudaFuncSetAttribute(rssm_kernel, cudaFuncAttributeMaxDynamicSharedMemorySize, SMEMB);
    int dev = 0, nsm = 0, occ = 0;
    cudaGetDevice(&dev);
    cudaDeviceGetAttribute(&nsm, cudaDevAttrMultiProcessorCount, dev);
    cudaOccupancyMaxActiveBlocksPerMultiprocessor(&occ, rssm_kernel, NTHR, SMEMB);
    if (occ < 1) occ = 1;
    int G = nsm * occ;
    if (G > 148) G = 148;
    rssm_kernel<<<G, NTHR, SMEMB>>>(prev_z, prev_h, actions, emb, dones, post_noise,
                                    W_az, b_az, W_ih, W_hh, b_ih, b_hh, W_ha, b_ha,
                                    W_prior, b_prior, W_he, b_he, W_post, b_post, out);
}

// round 15
// speedup vs baseline: 1.2649x; 1.2649x over previous
#include <cuda_runtime.h>
#include <cuda_bf16.h>
#include <math.h>

#define ADIM 6
#define ZDIM 32
#define HDIM 512
#define EDIM 1024
#define BATCH 256
#define TSTEPS 64
#define NTHR 512
#define SMEMB 53248
#define HP 256   /* pairs per row (HDIM/2) */

#define OFF_Z  (BATCH*TSTEPS*HDIM)
#define OFF_PM (OFF_Z + BATCH*TSTEPS*ZDIM)
#define OFF_PS (OFF_PM + BATCH*TSTEPS*ZDIM)
#define OFF_QM (OFF_PS + BATCH*TSTEPS*ZDIM)
#define OFF_QS (OFF_QM + BATCH*TSTEPS*ZDIM)

// scratch. pre* layout: [t][b][h]
__device__ __align__(128) float g_preAZ[TSTEPS*BATCH*HDIM];
__device__ __align__(128) float g_preHA[TSTEPS*BATCH*HDIM];
__device__ __align__(128) float g_preHE[TSTEPS*BATCH*HDIM];
__device__ __align__(128) float g_Gp[3][BATCH*3072];
__device__ __align__(128) float g_Hp[8][BATCH*1024];
__device__ __align__(128) float g_h[BATCH*HDIM];
__device__ __align__(128) float g_z[BATCH*ZDIM];
__device__ __align__(128) float g_WazzT[ZDIM*HDIM];
// bf16 pair planes: word = (bf16(k+1)<<16)|bf16(k)
__device__ __align__(128) unsigned g_WihHp[1536*HP], g_WihLp[1536*HP];
__device__ __align__(128) unsigned g_WhhHp[1536*HP], g_WhhLp[1536*HP];
__device__ __align__(128) unsigned g_WhaHp[HDIM*HP], g_WhaLp[HDIM*HP];
__device__ __align__(128) unsigned g_WheHp[HDIM*HP], g_WheLp[HDIM*HP];
__device__ __align__(128) unsigned g_hHp[BATCH*HP], g_hLp[BATCH*HP];
__device__ __align__(128) unsigned g_xHp[BATCH*HP], g_xLp[BATCH*HP];
__device__ volatile unsigned g_arrive = 0;
__device__ volatile unsigned g_epoch = 0;

__device__ __forceinline__ float sigmoidf_(float x) { return 1.f/(1.f+expf(-x)); }
__device__ __forceinline__ float softplusf_(float x) {
    return fmaxf(x, 0.f) + log1pf(expf(-fabsf(x)));
}
__device__ __forceinline__ float4 ld4(const float* p) { return *(const float4*)p; }
__device__ __forceinline__ float4 ld4cg(const float* p) { return __ldcg((const float4*)p); }
__device__ __forceinline__ void st2cg(float* p, float2 v) { __stcg((float2*)p, v); }

// split x0,x1 into hi-pair word and lo-pair word (even k in low half)
__device__ __forceinline__ void split2(float x0, float x1, unsigned &hw, unsigned &lw) {
    unsigned h0 = (unsigned)__bfloat16_as_ushort(__float2bfloat16_rn(x0));
    unsigned h1 = (unsigned)__bfloat16_as_ushort(__float2bfloat16_rn(x1));
    hw = h0 | (h1 << 16);
    float l0 = x0 - __uint_as_float(h0 << 16);
    float l1 = x1 - __uint_as_float(h1 << 16);
    unsigned L0 = (unsigned)__bfloat16_as_ushort(__float2bfloat16_rn(l0));
    unsigned L1 = (unsigned)__bfloat16_as_ushort(__float2bfloat16_rn(l1));
    lw = L0 | (L1 << 16);
}

__device__ __forceinline__ void mma_bf16(float4 &d, unsigned a0, unsigned a1,
                                         unsigned a2, unsigned a3,
                                         unsigned b0, unsigned b1) {
    asm volatile(
        "mma.sync.aligned.m16n8k16.row.col.f32.bf16.bf16.f32 "
        "{%0,%1,%2,%3},{%4,%5,%6,%7},{%8,%9},{%0,%1,%2,%3};"
        : "+f"(d.x), "+f"(d.y), "+f"(d.z), "+f"(d.w)
        : "r"(a0), "r"(a1), "r"(a2), "r"(a3), "r"(b0), "r"(b1));
}

// tf32 helpers for the once-only preHE prologue
__device__ __forceinline__ unsigned tf32of(float x) {
    unsigned u; asm("cvt.rna.tf32.f32 %0, %1;" : "=r"(u) : "f"(x)); return u;
}
__device__ __forceinline__ void split_tf32(float x, unsigned &hi, unsigned &lo) {
    hi = tf32of(x);
    lo = tf32of(x - __uint_as_float(hi));
}
__device__ __forceinline__ void mma_tf32(float4 &d, unsigned a0, unsigned a1,
                                         unsigned a2, unsigned a3,
                                         unsigned b0, unsigned b1) {
    asm volatile(
        "mma.sync.aligned.m16n8k8.row.col.f32.tf32.tf32.f32 "
        "{%0,%1,%2,%3},{%4,%5,%6,%7},{%8,%9},{%0,%1,%2,%3};"
        : "+f"(d.x), "+f"(d.y), "+f"(d.z), "+f"(d.w)
        : "r"(a0), "r"(a1), "r"(a2), "r"(a3), "r"(b0), "r"(b1));
}

// Fence-free grid barrier (scoped atomics, no CCTL.IVALL).
__device__ __forceinline__ void gsync(int G) {
    __syncthreads();
    if (threadIdx.x == 0) {
        unsigned e = g_epoch;
        unsigned old;
        asm volatile("atom.acq_rel.gpu.global.add.u32 %0, [%1], %2;"
                     : "=r"(old) : "l"((unsigned*)&g_arrive), "r"(1u) : "memory");
        if (old == (unsigned)(G - 1)) {
            g_arrive = 0;
            asm volatile("st.release.gpu.global.u32 [%0], %1;"
                         :: "l"((unsigned*)&g_epoch), "r"(e + 1u) : "memory");
        } else {
            unsigned cur;
            do {
                __nanosleep(32);
                asm volatile("ld.acquire.gpu.global.u32 %0, [%1];"
                             : "=r"(cur) : "l"((unsigned*)&g_epoch) : "memory");
            } while (cur == e);
        }
    }
    __syncthreads();
}

// ---------------------------------------------------------------------------
// bf16 3-term 128x128 tile GEMM. Operands are pair-plane arrays (ldp pairs).
// 16 warps (4x4), warp tile 32x32, k16 per slab. Smem planes stride 136.
// ---------------------------------------------------------------------------
__device__ __forceinline__ void gemm128_b3(
    const unsigned* __restrict__ AH, const unsigned* __restrict__ AL, int ldpA,
    const unsigned* __restrict__ BH, const unsigned* __restrict__ BL, int ldpB,
    int KT, unsigned* smu, float4 (&acc)[2][4])
{
    unsigned* AsH = smu;
    unsigned* AsL = smu + 1088;
    unsigned* BsH = smu + 2176;
    unsigned* BsL = smu + 3264;
    const int tid = threadIdx.x;
    const bool isA = (tid < 256);
    const int sr = (tid & 255) >> 1;    // row 0..127
    const int spk = (tid & 1) * 4;      // pair base 0 or 4
    const int ldp = isA ? ldpA : ldpB;
    const unsigned* gH = (isA ? AH : BH) + sr*ldp + spk;
    const unsigned* gL = (isA ? AL : BL) + sr*ldp + spk;
    unsigned* dH = isA ? AsH : BsH;
    unsigned* dL = isA ? AsL : BsL;
    const int lane = tid & 31, warp = tid >> 5;
    const int wm = (warp & 3) * 32, wn = (warp >> 2) * 32;
    const int gid = lane >> 2, tig = lane & 3;
    uint4 vh = __ldcg((const uint4*)gH);
    uint4 vl = __ldcg((const uint4*)gL);
    #pragma unroll 1
    for (int kt = 1; kt <= KT; kt++) {
        __syncthreads();
        dH[(spk+0)*136+sr]=vh.x; dH[(spk+1)*136+sr]=vh.y;
        dH[(spk+2)*136+sr]=vh.z; dH[(spk+3)*136+sr]=vh.w;
        dL[(spk+0)*136+sr]=vl.x; dL[(spk+1)*136+sr]=vl.y;
        dL[(spk+2)*136+sr]=vl.z; dL[(spk+3)*136+sr]=vl.w;
        __syncthreads();
        if (kt < KT) {
            vh = __ldcg((const uint4*)(gH + kt*8));
            vl = __ldcg((const uint4*)(gL + kt*8));
        }
        unsigned aH[2][4], aL[2][4];
        #pragma unroll
        for (int i = 0; i < 2; i++) {
            int r0 = wm + i*16 + gid;
            aH[i][0] = AsH[tig*136 + r0];     aH[i][1] = AsH[tig*136 + r0 + 8];
            aH[i][2] = AsH[(4+tig)*136 + r0]; aH[i][3] = AsH[(4+tig)*136 + r0 + 8];
            aL[i][0] = AsL[tig*136 + r0];     aL[i][1] = AsL[tig*136 + r0 + 8];
            aL[i][2] = AsL[(4+tig)*136 + r0]; aL[i][3] = AsL[(4+tig)*136 + r0 + 8];
        }
        unsigned bH[4][2], bL[4][2];
        #pragma unroll
        for (int j = 0; j < 4; j++) {
            int n0 = wn + j*8 + gid;
            bH[j][0] = BsH[tig*136 + n0]; bH[j][1] = BsH[(4+tig)*136 + n0];
            bL[j][0] = BsL[tig*136 + n0]; bL[j][1] = BsL[(4+tig)*136 + n0];
        }
        #pragma unroll
        for (int i = 0; i < 2; i++)
            #pragma unroll
            for (int j = 0; j < 4; j++) {
                mma_bf16(acc[i][j], aH[i][0],aH[i][1],aH[i][2],aH[i][3], bH[j][0],bH[j][1]);
                mma_bf16(acc[i][j], aH[i][0],aH[i][1],aH[i][2],aH[i][3], bL[j][0],bL[j][1]);
                mma_bf16(acc[i][j], aL[i][0],aL[i][1],aL[i][2],aL[i][3], bH[j][0],bH[j][1]);
            }
    }
}

// tf32 on-the-fly 128x128 core (prologue preHE only; runs once)
__device__ __forceinline__ void gemm128_tc(
    const float* __restrict__ A, int lda, const float* __restrict__ B, int ldb,
    int KT, float* As, float* Bs, float4 (&acc)[2][4])
{
    const int tid = threadIdx.x;
    const int lr = tid >> 2, lk = (tid & 3) << 2;
    const int lane = tid & 31, warp = tid >> 5;
    const int wm = (warp & 3) * 32, wn = (warp >> 2) * 32;
    const int gid = lane >> 2, tig = lane & 3;
    const float* Ap = A + lr*lda + lk;
    const float* Bp = B + lr*ldb + lk;
    float4 av = ld4(Ap), bv = ld4(Bp);
    #pragma unroll 1
    for (int kt = 1; kt <= KT; kt++) {
        __syncthreads();
        As[(lk+0)*132+lr]=av.x; As[(lk+1)*132+lr]=av.y; As[(lk+2)*132+lr]=av.z; As[(lk+3)*132+lr]=av.w;
        Bs[(lk+0)*132+lr]=bv.x; Bs[(lk+1)*132+lr]=bv.y; Bs[(lk+2)*132+lr]=bv.z; Bs[(lk+3)*132+lr]=bv.w;
        __syncthreads();
        if (kt < KT) { av = ld4(Ap + kt*16); bv = ld4(Bp + kt*16); }
        #pragma unroll
        for (int kq = 0; kq < 2; kq++) {
            const int kA = kq*8 + tig;
            unsigned ah[2][4], al[2][4];
            #pragma unroll
            for (int i = 0; i < 2; i++) {
                int mi = wm + i*16 + gid;
                split_tf32(As[kA*132 + mi],        ah[i][0], al[i][0]);
                split_tf32(As[kA*132 + mi + 8],    ah[i][1], al[i][1]);
                split_tf32(As[(kA+4)*132 + mi],    ah[i][2], al[i][2]);
                split_tf32(As[(kA+4)*132 + mi + 8],ah[i][3], al[i][3]);
            }
            unsigned bh[4][2], bl[4][2];
            #pragma unroll
            for (int j = 0; j < 4; j++) {
                int nj = wn + j*8 + gid;
                split_tf32(Bs[kA*132 + nj],     bh[j][0], bl[j][0]);
                split_tf32(Bs[(kA+4)*132 + nj], bh[j][1], bl[j][1]);
            }
            #pragma unroll
            for (int i = 0; i < 2; i++)
                #pragma unroll
                for (int j = 0; j < 4; j++) {
                    mma_tf32(acc[i][j], ah[i][0],ah[i][1],ah[i][2],ah[i][3], bh[j][0],bh[j][1]);
                    mma_tf32(acc[i][j], ah[i][0],ah[i][1],ah[i][2],ah[i][3], bl[j][0],bl[j][1]);
                    mma_tf32(acc[i][j], al[i][0],al[i][1],al[i][2],al[i][3], bh[j][0],bh[j][1]);
                }
        }
    }
}

__device__ __forceinline__ float gru1(float ir, float iz, float inn,
                                      float hr, float hz, float hn, float hp) {
    float rr = sigmoidf_(ir + hr);
    float u = sigmoidf_(iz + hz);
    float n = tanhf(inn + rr*hn);
    return (1.f - u)*n + u*hp;
}

__constant__ int c_kofsp[3] = {0, 88, 176};   // pair offsets
__constant__ int c_kcnt[3]  = {11, 11, 10};   // 16k slabs

__global__ __launch_bounds__(NTHR, 1) void rssm_kernel(
    const float* __restrict__ prev_z, const float* __restrict__ prev_h,
    const float* __restrict__ actions, const float* __restrict__ emb,
    const float* __restrict__ dones, const float* __restrict__ post_noise,
    const float* __restrict__ W_az, const float* __restrict__ b_az,
    const float* __restrict__ W_ih, const float* __restrict__ W_hh,
    const float* __restrict__ b_ih, const float* __restrict__ b_hh,
    const float* __restrict__ W_ha, const float* __restrict__ b_ha,
    const float* __restrict__ W_prior, const float* __restrict__ b_prior,
    const float* __restrict__ W_he, const float* __restrict__ b_he,
    const float* __restrict__ W_post, const float* __restrict__ b_post,
    float* __restrict__ out)
{
    extern __shared__ __align__(16) float sm[];
    unsigned* smu = (unsigned*)sm;
    const int tid = threadIdx.x, bid = blockIdx.x, G = gridDim.x;
    const int gthr = G*NTHR, gtid = bid*NTHR + tid;
    const int lane = tid & 31, warp = tid >> 5;
    const int wm = (warp & 3) * 32, wn = (warp >> 2) * 32;
    const int gid = lane >> 2, tig = lane & 3;

    // ===== P0: init, weight pair-split, action projections, preHE =====
    for (int i = gtid; i < BATCH*HP; i += gthr) {
        int b = i >> 8, kp = i & 255;
        float v0 = prev_h[b*HDIM + 2*kp], v1 = prev_h[b*HDIM + 2*kp + 1];
        g_h[b*HDIM + 2*kp] = v0; g_h[b*HDIM + 2*kp + 1] = v1;
        split2(v0, v1, g_hHp[i], g_hLp[i]);
    }
    for (int i = gtid; i < BATCH*ZDIM; i += gthr) g_z[i] = prev_z[i];
    for (int i = gtid; i < 1536*HP; i += gthr) {
        int n = i >> 8, kp = i & 255;
        split2(W_ih[n*HDIM + 2*kp], W_ih[n*HDIM + 2*kp + 1], g_WihHp[i], g_WihLp[i]);
        split2(W_hh[n*HDIM + 2*kp], W_hh[n*HDIM + 2*kp + 1], g_WhhHp[i], g_WhhLp[i]);
    }
    for (int i = gtid; i < HDIM*HP; i += gthr) {
        int n = i >> 8, kp = i & 255;
        split2(W_ha[n*(HDIM+ADIM) + 2*kp], W_ha[n*(HDIM+ADIM) + 2*kp + 1],
               g_WhaHp[i], g_WhaLp[i]);
        split2(W_he[n*1536 + 2*kp], W_he[n*1536 + 2*kp + 1],
               g_WheHp[i], g_WheLp[i]);
    }
    for (int i = gtid; i < ZDIM*HDIM; i += gthr)
        g_WazzT[i] = W_az[(i & 511)*(ZDIM+ADIM) + (i >> 9)];
    for (int tt = bid; tt < TSTEPS; tt += G) {
        float* waz = sm, *wha = sm + 3072, *actS = sm + 6144;
        __syncthreads();
        for (int e = tid; e < HDIM*ADIM; e += NTHR) {
            int h = e / ADIM, j = e - h*ADIM;
            waz[e] = W_az[h*(ZDIM+ADIM) + ZDIM + j];
            wha[e] = W_ha[h*(HDIM+ADIM) + HDIM + j];
        }
        for (int e = tid; e < BATCH*ADIM; e += NTHR) {
            int b = e / ADIM, j = e - b*ADIM;
            actS[e] = actions[(b*TSTEPS + tt)*ADIM + j];
        }
        __syncthreads();
        for (int e = tid; e < BATCH*HDIM; e += NTHR) {
            int b = e >> 9, h = e & 511;
            float pa = b_az[h], ph = b_ha[h];
            #pragma unroll
            for (int j = 0; j < ADIM; j++) {
                float a = actS[b*ADIM + j];
                pa += a * waz[h*ADIM + j];
                ph += a * wha[h*ADIM + j];
            }
            int o = (tt*BATCH + b)*HDIM + h;
            g_preAZ[o] = pa; g_preHA[o] = ph;
        }
        __syncthreads();
    }
    // preHE: 512 tasks, tf32 on-the-fly (runs once)
    for (int task = bid; task < 512; task += G) {
        int n = task & 3, m = task >> 2;
        float4 acc[2][4] = {};
        gemm128_tc(emb + (size_t)m*128*EDIM, EDIM,
                   W_he + (size_t)n*128*1536 + 512, 1536, 64, sm, sm + 2112, acc);
        #pragma unroll
        for (int i = 0; i < 2; i++)
            #pragma unroll
            for (int j = 0; j < 4; j++) {
                int row = m*128 + wm + i*16 + gid;
                int col = n*128 + wn + j*8 + tig*2;
                float b0 = b_he[col], b1 = b_he[col+1];
                int o0 = ((row & 63)*BATCH + (row >> 6))*HDIM + col;
                int r8 = row + 8;
                int o1 = ((r8 & 63)*BATCH + (r8 >> 6))*HDIM + col;
                *(float2*)(g_preHE + o0) = make_float2(acc[i][j].x + b0, acc[i][j].y + b1);
                *(float2*)(g_preHE + o1) = make_float2(acc[i][j].z + b0, acc[i][j].w + b1);
            }
    }
    gsync(G);
    // ===== P1: x(0) =====
    for (int i = gtid; i < BATCH*HP; i += gthr) {
        int b = i >> 8, cp = i & 255;
        float d = 1.f - dones[b*TSTEPS];
        float a0 = g_preAZ[b*HDIM + 2*cp], a1 = g_preAZ[b*HDIM + 2*cp + 1];
        #pragma unroll 8
        for (int k = 0; k < ZDIM; k++) {
            float zk = g_z[b*ZDIM + k]*d;
            a0 += zk * g_WazzT[k*HDIM + 2*cp];
            a1 += zk * g_WazzT[k*HDIM + 2*cp + 1];
        }
        unsigned hw, lw; split2(fmaxf(a0,0.f), fmaxf(a1,0.f), hw, lw);
        __stcg(g_xHp + i, hw); __stcg(g_xLp + i, lw);
    }
    gsync(G);

    for (int t = 0; t < TSTEPS; t++) {
        // ---- A: gate partials. 144 tasks = 48 tiles(128x128) x Ksplit3 ----
        for (int task = bid; task < 144; task += G) {
            int kc = task % 3, tile = task / 3;
            int n = tile % 24, m = tile / 24;
            int ko = c_kofsp[kc];
            size_t ao = (size_t)m*128*HP + ko;
            const unsigned* AH = ((n < 12) ? g_xHp : g_hHp) + ao;
            const unsigned* AL = ((n < 12) ? g_xLp : g_hLp) + ao;
            size_t bo = ((n < 12) ? (size_t)n : (size_t)(n-12))*128*HP + ko;
            const unsigned* BH = ((n < 12) ? g_WihHp : g_WhhHp) + bo;
            const unsigned* BL = ((n < 12) ? g_WihLp : g_WhhLp) + bo;
            float4 acc[2][4] = {};
            gemm128_b3(AH, AL, HP, BH, BL, HP, c_kcnt[kc], smu, acc);
            #pragma unroll
            for (int i = 0; i < 2; i++)
                #pragma unroll
                for (int j = 0; j < 4; j++) {
                    int row = m*128 + wm + i*16 + gid;
                    int col = n*128 + wn + j*8 + tig*2;
                    st2cg(&g_Gp[kc][row*3072 + col], make_float2(acc[i][j].x, acc[i][j].y));
                    st2cg(&g_Gp[kc][(row+8)*3072 + col], make_float2(acc[i][j].z, acc[i][j].w));
                }
        }
        gsync(G);
        // ---- B: combine 3 partials + GRU fuse + h_seq + h pair-split ----
        for (int i = gtid; i < BATCH*HDIM/4; i += gthr) {
            int b = i >> 7, j4 = (i & 127) << 2;
            const float* p0 = g_Gp[0] + b*3072 + j4;
            const float* p1 = g_Gp[1] + b*3072 + j4;
            const float* p2 = g_Gp[2] + b*3072 + j4;
            float4 gg[6];
            #pragma unroll
            for (int q = 0; q < 6; q++) {
                float4 a = ld4cg(p0 + q*512), bb = ld4cg(p1 + q*512), c = ld4cg(p2 + q*512);
                gg[q] = make_float4(a.x+bb.x+c.x, a.y+bb.y+c.y, a.z+bb.z+c.z, a.w+bb.w+c.w);
            }
            float4 bir = ld4(b_ih + j4), biz = ld4(b_ih + 512 + j4), bin = ld4(b_ih + 1024 + j4);
            float4 bhr = ld4(b_hh + j4), bhz = ld4(b_hh + 512 + j4), bhn = ld4(b_hh + 1024 + j4);
            float4 hp = ld4cg(g_h + i*4);
            float4 hv;
            hv.x = gru1(gg[0].x+bir.x, gg[1].x+biz.x, gg[2].x+bin.x, gg[3].x+bhr.x, gg[4].x+bhz.x, gg[5].x+bhn.x, hp.x);
            hv.y = gru1(gg[0].y+bir.y, gg[1].y+biz.y, gg[2].y+bin.y, gg[3].y+bhr.y, gg[4].y+bhz.y, gg[5].y+bhn.y, hp.y);
            hv.z = gru1(gg[0].z+bir.z, gg[1].z+biz.z, gg[2].z+bin.z, gg[3].z+bhr.z, gg[4].z+bhz.z, gg[5].z+bhn.z, hp.z);
            hv.w = gru1(gg[0].w+bir.w, gg[1].w+biz.w, gg[2].w+bin.w, gg[3].w+bhr.w, gg[4].w+bhz.w, gg[5].w+bhn.w, hp.w);
            __stcg((float4*)(g_h + i*4), hv);
            *(float4*)(out + (b*TSTEPS + t)*HDIM + j4) = hv;
            unsigned hw0, lw0, hw1, lw1;
            split2(hv.x, hv.y, hw0, lw0);
            split2(hv.z, hv.w, hw1, lw1);
            int cp = b*HP + (j4 >> 1);
            __stcg((uint2*)(g_hHp + cp), make_uint2(hw0, hw1));
            __stcg((uint2*)(g_hLp + cp), make_uint2(lw0, lw1));
        }
        gsync(G);
        // ---- C: hahe partials. 128 tasks = 16 tiles(128x128) x Ksplit8 (K=64) ----
        for (int task = bid; task < 128; task += G) {
            int kc = task & 7, tile = task >> 3;
            int n = tile & 7, m = tile >> 3;
            size_t ao = (size_t)m*128*HP + kc*32;
            size_t bo = ((n < 4) ? (size_t)n : (size_t)(n-4))*128*HP + kc*32;
            const unsigned* BH = ((n < 4) ? g_WhaHp : g_WheHp) + bo;
            const unsigned* BL = ((n < 4) ? g_WhaLp : g_WheLp) + bo;
            float4 acc[2][4] = {};
            gemm128_b3(g_hHp + ao, g_hLp + ao, HP, BH, BL, HP, 4, smu, acc);
            #pragma unroll
            for (int i = 0; i < 2; i++)
                #pragma unroll
                for (int j = 0; j < 4; j++) {
                    int row = m*128 + wm + i*16 + gid;
                    int col = n*128 + wn + j*8 + tig*2;
                    st2cg(&g_Hp[kc][row*1024 + col], make_float2(acc[i][j].x, acc[i][j].y));
                    st2cg(&g_Hp[kc][(row+8)*1024 + col], make_float2(acc[i][j].z, acc[i][j].w));
                }
        }
        gsync(G);
        // ---- D: 64 tasks x 4 rows: combine+relu, heads, z, x[t+1] ----
        for (int task = bid; task < 64; task += G) {
            int r0 = task*4;
            float* A8 = sm;          // 4 x 1028
            float* Ws = sm + 4112;   // 128 x 68
            __syncthreads();
            for (int e = tid; e < 4*1024; e += NTHR) {
                int r = e >> 10, c = e & 1023;
                int ro = (r0 + r)*1024 + c;
                float v = __ldcg(g_Hp[0]+ro) + __ldcg(g_Hp[1]+ro)
                        + __ldcg(g_Hp[2]+ro) + __ldcg(g_Hp[3]+ro)
                        + __ldcg(g_Hp[4]+ro) + __ldcg(g_Hp[5]+ro)
                        + __ldcg(g_Hp[6]+ro) + __ldcg(g_Hp[7]+ro);
                v += (c < 512) ? g_preHA[(t*BATCH + r0+r)*HDIM + c]
                               : g_preHE[(t*BATCH + r0+r)*HDIM + c - 512];
                A8[r*1028 + c] = fmaxf(v, 0.f);
            }
            const int c = tid & 127, rg = tid >> 7;
            const int aoff = (c < 64) ? 0 : 512;
            float acc = 0.f;
            for (int ch = 0; ch < 8; ch++) {
                __syncthreads();
                for (int e = tid; e < 512; e += NTHR) {
                    int c2 = e >> 2, k4 = (e & 3) << 4;
                    const float* Wr = (c2 < 64) ? W_prior + c2*HDIM : W_post + (c2-64)*HDIM;
                    #pragma unroll
                    for (int q = 0; q < 4; q++) {
                        float4 w = ld4(Wr + ch*64 + k4 + q*4);
                        Ws[c2*68 + k4 + q*4]   = w.x; Ws[c2*68 + k4 + q*4+1] = w.y;
                        Ws[c2*68 + k4 + q*4+2] = w.z; Ws[c2*68 + k4 + q*4+3] = w.w;
                    }
                }
                __syncthreads();
                const float* ab = A8 + rg*1028 + aoff + ch*64;
                #pragma unroll
                for (int k4 = 0; k4 < 64; k4 += 4) {
                    float4 w = ld4(Ws + c*68 + k4);
                    float4 a = ld4(ab + k4);
                    acc += a.x*w.x + a.y*w.y + a.z*w.z + a.w*w.w;
                }
            }
            __syncthreads();
            float* Q  = sm;        // 4 x 64 (A8 dead)
            float* zm = sm + 256;  // 4 x 32
            {
                int b = r0 + rg;
                float v = acc + ((c < 64) ? b_prior[c] : b_post[c-64]);
                if (c < 32)       out[OFF_PM + (b*TSTEPS + t)*ZDIM + c] = v;
                else if (c < 64)  out[OFF_PS + (b*TSTEPS + t)*ZDIM + c-32] = softplusf_(v);
                else              Q[rg*64 + (c-64)] = v;
            }
            __syncthreads();
            if (tid < 128) {
                int r = tid >> 5, j = tid & 31, b = r0 + r;
                float qm = Q[r*64 + j];
                float qs = softplusf_(Q[r*64 + 32 + j]);
                float z = qm + qs * post_noise[(b*TSTEPS + t)*ZDIM + j];
                int o = (b*TSTEPS + t)*ZDIM + j;
                out[OFF_QM + o] = qm; out[OFF_QS + o] = qs; out[OFF_Z + o] = z;
                if (t + 1 < TSTEPS)
                    zm[r*32 + j] = z * (1.f - dones[b*TSTEPS + t + 1]);
            }
            __syncthreads();
            if (t + 1 < TSTEPS) {
                for (int e = tid; e < 4*HP; e += NTHR) {
                    int r = e >> 8, cp = e & 255;
                    float a0 = g_preAZ[((t+1)*BATCH + r0+r)*HDIM + 2*cp];
                    float a1 = g_preAZ[((t+1)*BATCH + r0+r)*HDIM + 2*cp + 1];
                    #pragma unroll 8
                    for (int k = 0; k < ZDIM; k++) {
                        float zk = zm[r*32 + k];
                        a0 += zk * g_WazzT[k*HDIM + 2*cp];
                        a1 += zk * g_WazzT[k*HDIM + 2*cp + 1];
                    }
                    unsigned hw, lw; split2(fmaxf(a0,0.f), fmaxf(a1,0.f), hw, lw);
                    int xo = (r0+r)*HP + cp;
                    __stcg(g_xHp + xo, hw); __stcg(g_xLp + xo, lw);
                }
            }
            __syncthreads();
        }
        if (t + 1 < TSTEPS) gsync(G);
    }
}

extern "C" void kernel_launch(void* const* d_in, const int* in_sizes, int n_in,
                              void* d_out, int out_size) {
    const float* prev_z = (const float*)d_in[0];
    const float* prev_h = (const float*)d_in[1];
    const float* actions = (const float*)d_in[2];
    const float* emb = (const float*)d_in[3];
    const float* dones = (const float*)d_in[4];
    const float* post_noise = (const float*)d_in[6];
    const float* W_az = (const float*)d_in[7];
    const float* b_az = (const float*)d_in[8];
    const float* W_ih = (const float*)d_in[9];
    const float* W_hh = (const float*)d_in[10];
    const float* b_ih = (const float*)d_in[11];
    const float* b_hh = (const float*)d_in[12];
    const float* W_ha = (const float*)d_in[13];
    const float* b_ha = (const float*)d_in[14];
    const float* W_prior = (const float*)d_in[15];
    const float* b_prior = (const float*)d_in[16];
    const float* W_he = (const float*)d_in[17];
    const float* b_he = (const float*)d_in[18];
    const float* W_post = (const float*)d_in[19];
    const float* b_post = (const float*)d_in[20];
    float* out = (float*)d_out;

    cudaFuncSetAttribute(rssm_kernel, cudaFuncAttributeMaxDynamicSharedMemorySize, SMEMB);
    int dev = 0, nsm = 0, occ = 0;
    cudaGetDevice(&dev);
    cudaDeviceGetAttribute(&nsm, cudaDevAttrMultiProcessorCount, dev);
    cudaOccupancyMaxActiveBlocksPerMultiprocessor(&occ, rssm_kernel, NTHR, SMEMB);
    if (occ < 1) occ = 1;
    int G = nsm * occ;
    if (G > 148) G = 148;
    rssm_kernel<<<G, NTHR, SMEMB>>>(prev_z, prev_h, actions, emb, dones, post_noise,
                                    W_az, b_az, W_ih, W_hh, b_ih, b_hh, W_ha, b_ha,
                                    W_prior, b_prior, W_he, b_he, W_post, b_post, out);
}